// round 6
// baseline (speedup 1.0000x reference)
#include <cuda_runtime.h>
#include <cstdint>
#include <cstddef>

#define D 768
#define N_LAYERS 4
#define MAXN 50000
#define MAXE 100000

// ---------------- static scratch (allocation-free rule) ----------------
__device__ float g_e  [(size_t)MAXE * D];   // bond/edge features e  [E,768]
__device__ float g_tmp[(size_t)MAXE * D];   // GEMM hidden buffer   [E,768]
__device__ float g_hA [(size_t)MAXN * D];
__device__ float g_hB [(size_t)MAXN * D];
__device__ float g_agg[(size_t)MAXN * D];
__device__ float g_wt [(size_t)12 * D * D]; // transposed+tf32-rounded+k-interleaved weights

// ---------------- tiny helpers ----------------
__device__ __forceinline__ float gelu_f(float x) {
    const float k0 = 0.7978845608028654f;
    const float k1 = 0.044715f;
    return 0.5f * x * (1.0f + tanhf(k0 * (x + k1 * x * x * x)));
}
template <int ACT>
__device__ __forceinline__ float actf(float x) {
    if (ACT == 1) return fmaxf(x, 0.0f);
    if (ACT == 2) return gelu_f(x);
    return x;
}
__device__ __forceinline__ float tf32r(float x) {  // round-to-nearest tf32, kept in fp32
    uint32_t r;
    asm("cvt.rna.tf32.f32 %0, %1;" : "=r"(r) : "f"(x));
    return __uint_as_float(r);
}
__device__ __forceinline__ void block_reduce2(float& s1, float& s2, float* shm) {
    #pragma unroll
    for (int o = 16; o > 0; o >>= 1) {
        s1 += __shfl_xor_sync(0xffffffffu, s1, o);
        s2 += __shfl_xor_sync(0xffffffffu, s2, o);
    }
    int wid = threadIdx.x >> 5, lane = threadIdx.x & 31;
    if (lane == 0) { shm[wid] = s1; shm[8 + wid] = s2; }
    __syncthreads();
    float a = 0.f, b = 0.f;
    #pragma unroll
    for (int i = 0; i < 8; i++) { a += shm[i]; b += shm[8 + i]; }
    s1 = a; s2 = b;
}

__device__ __forceinline__ void cp_async16(void* s, const void* g) {
    uint32_t sa = (uint32_t)__cvta_generic_to_shared(s);
    asm volatile("cp.async.cg.shared.global [%0], [%1], 16;" :: "r"(sa), "l"(g));
}
__device__ __forceinline__ void mma_tf32(float* c, const uint32_t* a, uint32_t b0, uint32_t b1) {
    asm volatile(
        "mma.sync.aligned.m16n8k8.row.col.f32.tf32.tf32.f32 "
        "{%0,%1,%2,%3},{%4,%5,%6,%7},{%8,%9},{%0,%1,%2,%3};"
        : "+f"(c[0]), "+f"(c[1]), "+f"(c[2]), "+f"(c[3])
        : "r"(a[0]), "r"(a[1]), "r"(a[2]), "r"(a[3]), "r"(b0), "r"(b1));
}

// ---------------- optimized tf32 mma.sync GEMM ----------------
// C[M,768] = act(A[M,768] @ Wt^T + bias)
// Wt: [N=768][K=768] row-major, K interleaved per 8-group (0,4,1,5,2,6,3,7),
// values pre-rounded to tf32 -> no CVT in the mainloop.
// CTA tile 128(M) x 256(N), 512 threads (warp grid 4 M x 4 N, warp tile 32x64),
// BK=32, 3-stage cp.async pipeline.
#define BM 128
#define BN 256
#define BK 32
#define NT (D / BK)          // 24
#define NSTAGE 3
#define SA_S 36              // A smem stride (floats): (4*gr + tig) distinct mod 32 -> conflict-free
#define SB_S 40              // B smem stride (floats): S/2 == 4 mod 16 -> LDS.64 conflict-free
#define A_BYTES (BM * SA_S * 4)             // 18432
#define STAGE_BYTES (A_BYTES + BN * SB_S * 4)  // 18432 + 40960 = 59392
#define GEMM_THREADS 512
#define GEMM_SMEM (NSTAGE * STAGE_BYTES)    // 178176 B

template <int ACT, bool ROUND>
__global__ void __launch_bounds__(GEMM_THREADS, 1)
gemm_kernel(const float* __restrict__ A, const float* __restrict__ Wt,
            const float* __restrict__ bias, float* __restrict__ C, int M)
{
    extern __shared__ char smem[];
    const int t  = threadIdx.x;
    const int m0 = blockIdx.y * BM;
    const int n0 = blockIdx.x * BN;

    auto load_stage = [&](int s, int kt) {
        char* abuf = smem + s * STAGE_BYTES;
        char* bbuf = abuf + A_BYTES;
        // A: 128 rows x 32 floats = 1024 16B-chunks
        #pragma unroll
        for (int i = 0; i < 2; i++) {
            int q = t + i * GEMM_THREADS;
            int row = q >> 3, c = q & 7;
            int m = m0 + row; m = (m < M) ? m : (M - 1);   // clamp; garbage rows never stored
            cp_async16(abuf + (row * SA_S + c * 4) * 4, A + (size_t)m * D + kt * BK + c * 4);
        }
        // B: 256 rows x 32 floats = 2048 16B-chunks (rows are pre-interleaved in global)
        #pragma unroll
        for (int i = 0; i < 4; i++) {
            int q = t + i * GEMM_THREADS;
            int row = q >> 3, c = q & 7;
            cp_async16(bbuf + (row * SB_S + c * 4) * 4, Wt + (size_t)(n0 + row) * D + kt * BK + c * 4);
        }
    };

    float acc[2][8][4];
    #pragma unroll
    for (int i = 0; i < 2; i++)
        #pragma unroll
        for (int j = 0; j < 8; j++)
            #pragma unroll
            for (int k = 0; k < 4; k++) acc[i][j][k] = 0.f;

    #pragma unroll
    for (int s = 0; s < NSTAGE; s++) {
        load_stage(s, s);
        asm volatile("cp.async.commit_group;" ::: "memory");
    }

    const int lane = t & 31, wid = t >> 5;
    const int wm = (wid & 3) * 32;      // 4 warps along M (128)
    const int wn = (wid >> 2) * 64;     // 4 warps along N (256)
    const int gr = lane >> 2, tig = lane & 3;

    for (int kt = 0; kt < NT; ++kt) {
        const int s = kt % NSTAGE;
        asm volatile("cp.async.wait_group %0;" :: "n"(NSTAGE - 1) : "memory");
        __syncthreads();
        const float* sa = (const float*)(smem + s * STAGE_BYTES);
        const float* sb = (const float*)(smem + s * STAGE_BYTES + A_BYTES);
        #pragma unroll
        for (int kk8 = 0; kk8 < BK; kk8 += 8) {
            uint32_t af[2][4];
            #pragma unroll
            for (int mi = 0; mi < 2; mi++) {
                int r = wm + mi * 16 + gr;
                af[mi][0] = __float_as_uint(sa[r * SA_S + kk8 + tig]);
                af[mi][1] = __float_as_uint(sa[(r + 8) * SA_S + kk8 + tig]);
                af[mi][2] = __float_as_uint(sa[r * SA_S + kk8 + tig + 4]);
                af[mi][3] = __float_as_uint(sa[(r + 8) * SA_S + kk8 + tig + 4]);
            }
            #pragma unroll
            for (int ni = 0; ni < 8; ni++) {
                // interleaved layout: (k=kk8+tig, k=kk8+tig+4) adjacent -> one LDS.64
                const uint2 bv = *(const uint2*)(sb + (wn + ni * 8 + gr) * SB_S + kk8 + tig * 2);
                mma_tf32(acc[0][ni], af[0], bv.x, bv.y);
                mma_tf32(acc[1][ni], af[1], bv.x, bv.y);
            }
        }
        __syncthreads();                 // stage s fully consumed before refill
        if (kt + NSTAGE < NT) load_stage(s, kt + NSTAGE);
        asm volatile("cp.async.commit_group;" ::: "memory");
    }

    // epilogue: bias + activation (+ optional tf32 rounding) + store
    #pragma unroll
    for (int mi = 0; mi < 2; mi++) {
        int row0 = m0 + wm + mi * 16 + gr;
        #pragma unroll
        for (int ni = 0; ni < 8; ni++) {
            int col = n0 + wn + ni * 8 + tig * 2;
            float bv0 = __ldg(bias + col), bv1 = __ldg(bias + col + 1);
            float v0 = actf<ACT>(acc[mi][ni][0] + bv0);
            float v1 = actf<ACT>(acc[mi][ni][1] + bv1);
            float v2 = actf<ACT>(acc[mi][ni][2] + bv0);
            float v3 = actf<ACT>(acc[mi][ni][3] + bv1);
            if (ROUND) { v0 = tf32r(v0); v1 = tf32r(v1); v2 = tf32r(v2); v3 = tf32r(v3); }
            if (row0 < M)
                *(float2*)(C + (size_t)row0 * D + col) = make_float2(v0, v1);
            if (row0 + 8 < M)
                *(float2*)(C + (size_t)(row0 + 8) * D + col) = make_float2(v2, v3);
        }
    }
}

// ---------------- weight transpose + tf32 round + k-interleave ----------------
// Wt[n][k'] = rna_tf32(W[srck(k')][n]),  srck within each 32-chunk:
// k' = kk*8 + tig*2 + s  ->  k = kk*8 + tig + 4*s   (pairs (k,k+4) made adjacent)
__global__ void transpose_round_kernel(const float* __restrict__ W, float* __restrict__ Wt) {
    __shared__ float tile[32][33];
    int bx = blockIdx.x * 32;   // n block
    int by = blockIdx.y * 32;   // k block
    int tx = threadIdx.x, ty = threadIdx.y;   // 32 x 8
    #pragma unroll
    for (int j = 0; j < 32; j += 8)
        tile[ty + j][tx] = W[(size_t)(by + ty + j) * D + bx + tx];   // tile[k_local][n_local]
    __syncthreads();
    int kk  = tx >> 3;
    int tig = (tx & 7) >> 1;
    int s   = tx & 1;
    int srck = kk * 8 + tig + 4 * s;
    #pragma unroll
    for (int j = 0; j < 32; j += 8)
        Wt[(size_t)(bx + ty + j) * D + by + tx] = tf32r(tile[srck][ty + j]);
}

// ---------------- in-place tf32 rounding (pre-GEMM on agg) ----------------
__global__ void round_tf32_kernel(float4* __restrict__ p, int n4) {
    int i = blockIdx.x * blockDim.x + threadIdx.x;
    if (i < n4) {
        float4 v = p[i];
        v.x = tf32r(v.x); v.y = tf32r(v.y); v.z = tf32r(v.z); v.w = tf32r(v.w);
        p[i] = v;
    }
}

// ---------------- embedding sum + LayerNorm (tf32-rounded output) ----------------
__global__ void embed_ln_kernel(const int* __restrict__ ids,
                                const float* __restrict__ emb,
                                const float* __restrict__ g,
                                const float* __restrict__ bta,
                                float* __restrict__ out,
                                int F, int V) {
    int n = blockIdx.x;
    int t = threadIdx.x;
    __shared__ int   sid[16];
    __shared__ float shm[16];
    if (t < F) sid[t] = ids[(size_t)n * F + t];
    __syncthreads();

    float x[3];
    #pragma unroll
    for (int j = 0; j < 3; j++) {
        int d = t + j * 256;
        float s = 0.f;
        for (int f = 0; f < F; f++)
            s += emb[((size_t)(f * V + sid[f])) * D + d];
        x[j] = s;
    }
    float s1 = x[0] + x[1] + x[2];
    float s2 = x[0]*x[0] + x[1]*x[1] + x[2]*x[2];
    block_reduce2(s1, s2, shm);
    float mean = s1 * (1.0f / D);
    float var  = s2 * (1.0f / D) - mean * mean;
    float inv  = rsqrtf(var + 1e-5f);
    float* o = out + (size_t)n * D;
    #pragma unroll
    for (int j = 0; j < 3; j++) {
        int d = t + j * 256;
        o[d] = tf32r((x[j] - mean) * inv * g[d] + bta[d]);
    }
}

// ---------------- edge message: agg[dst] += relu(h[src] + e) ----------------
__global__ void edge_msg_kernel(const int* __restrict__ ei,
                                const float* __restrict__ h,
                                const float* __restrict__ e,
                                float* __restrict__ agg, int E) {
    int eid = blockIdx.x;
    int src = __ldg(ei + eid);
    int dst = __ldg(ei + E + eid);
    int t = threadIdx.x;  // 192 threads * float4 = 768
    float4 hv = *((const float4*)(h + (size_t)src * D) + t);
    float4 ev = *((const float4*)(e + (size_t)eid * D) + t);
    float4 m;
    m.x = fmaxf(hv.x + ev.x, 0.f);
    m.y = fmaxf(hv.y + ev.y, 0.f);
    m.z = fmaxf(hv.z + ev.z, 0.f);
    m.w = fmaxf(hv.w + ev.w, 0.f);
    float* a = agg + (size_t)dst * D + t * 4;
    atomicAdd(a + 0, m.x);
    atomicAdd(a + 1, m.y);
    atomicAdd(a + 2, m.z);
    atomicAdd(a + 3, m.w);
}

// ---------------- fused gelu + residual + LayerNorm (+ agg init for next layer) ----------------
__global__ void ln_res_kernel(const float* __restrict__ z,
                              const float* __restrict__ hin,
                              const float* __restrict__ g,
                              const float* __restrict__ bta,
                              float* __restrict__ out,
                              float* __restrict__ aggc) {
    int n = blockIdx.x;
    int t = threadIdx.x;
    __shared__ float shm[16];
    float x[3];
    #pragma unroll
    for (int j = 0; j < 3; j++) {
        int d = t + j * 256;
        x[j] = gelu_f(z[(size_t)n * D + d]) + hin[(size_t)n * D + d];
    }
    float s1 = x[0] + x[1] + x[2];
    float s2 = x[0]*x[0] + x[1]*x[1] + x[2]*x[2];
    block_reduce2(s1, s2, shm);
    float mean = s1 * (1.0f / D);
    float var  = s2 * (1.0f / D) - mean * mean;
    float inv  = rsqrtf(var + 1e-5f);
    #pragma unroll
    for (int j = 0; j < 3; j++) {
        int d = t + j * 256;
        float r = (x[j] - mean) * inv * g[d] + bta[d];
        out[(size_t)n * D + d] = r;
        if (aggc) aggc[(size_t)n * D + d] = r;
    }
}

__global__ void copy_kernel(const float4* __restrict__ src, float4* __restrict__ dst, int n4) {
    int i = blockIdx.x * blockDim.x + threadIdx.x;
    if (i < n4) dst[i] = src[i];
}

// ---------------- host orchestration ----------------
extern "C" void kernel_launch(void* const* d_in, const int* in_sizes, int n_in,
                              void* d_out, int out_size) {
    const int*   x          = (const int*)d_in[0];
    const int*   edge_attr  = (const int*)d_in[1];
    const int*   edge_index = (const int*)d_in[2];
    const float* atom_emb   = (const float*)d_in[3];
    const float* atom_ln_g  = (const float*)d_in[4];
    const float* atom_ln_b  = (const float*)d_in[5];
    const float* atom_w1    = (const float*)d_in[6];
    const float* atom_b1    = (const float*)d_in[7];
    const float* atom_w2    = (const float*)d_in[8];
    const float* atom_b2    = (const float*)d_in[9];
    const float* bond_emb   = (const float*)d_in[10];
    const float* bond_ln_g  = (const float*)d_in[11];
    const float* bond_ln_b  = (const float*)d_in[12];
    const float* bond_w1    = (const float*)d_in[13];
    const float* bond_b1    = (const float*)d_in[14];
    const float* bond_w2    = (const float*)d_in[15];
    const float* bond_b2    = (const float*)d_in[16];
    const float* conv_w1    = (const float*)d_in[17];
    const float* conv_b1    = (const float*)d_in[18];
    const float* conv_w2    = (const float*)d_in[19];
    const float* conv_b2    = (const float*)d_in[20];
    const float* ln_g       = (const float*)d_in[21];
    const float* ln_b       = (const float*)d_in[22];
    float* out = (float*)d_out;

    int N = in_sizes[0] / 9;
    int E = in_sizes[1] / 3;
    if (N > MAXN) N = MAXN;
    if (E > MAXE) E = MAXE;

    float *pe, *ptmp, *phA, *phB, *pagg, *pwt;
    cudaGetSymbolAddress((void**)&pe,   g_e);
    cudaGetSymbolAddress((void**)&ptmp, g_tmp);
    cudaGetSymbolAddress((void**)&phA,  g_hA);
    cudaGetSymbolAddress((void**)&phB,  g_hB);
    cudaGetSymbolAddress((void**)&pagg, g_agg);
    cudaGetSymbolAddress((void**)&pwt,  g_wt);

    cudaFuncSetAttribute(gemm_kernel<0, false>, cudaFuncAttributeMaxDynamicSharedMemorySize, GEMM_SMEM);
    cudaFuncSetAttribute(gemm_kernel<1, true>,  cudaFuncAttributeMaxDynamicSharedMemorySize, GEMM_SMEM);
    cudaFuncSetAttribute(gemm_kernel<2, true>,  cudaFuncAttributeMaxDynamicSharedMemorySize, GEMM_SMEM);

    // ---- transpose + tf32-round + interleave all 12 weight matrices ----
    dim3 tgrid(D / 32, D / 32), tblk(32, 8);
    auto WT = [&](int i) { return pwt + (size_t)i * D * D; };
    transpose_round_kernel<<<tgrid, tblk>>>(atom_w1, WT(0));
    transpose_round_kernel<<<tgrid, tblk>>>(atom_w2, WT(1));
    transpose_round_kernel<<<tgrid, tblk>>>(bond_w1, WT(2));
    transpose_round_kernel<<<tgrid, tblk>>>(bond_w2, WT(3));
    for (int l = 0; l < N_LAYERS; l++) {
        transpose_round_kernel<<<tgrid, tblk>>>(conv_w1 + (size_t)l * D * D, WT(4 + l));
        transpose_round_kernel<<<tgrid, tblk>>>(conv_w2 + (size_t)l * D * D, WT(8 + l));
    }

    dim3 gN(D / BN, (N + BM - 1) / BM);
    dim3 gE(D / BN, (E + BM - 1) / BM);

    // ---- atom encode: h = enc(x) ----
    embed_ln_kernel<<<N, 256>>>(x, atom_emb, atom_ln_g, atom_ln_b, pagg, 9, 128);
    gemm_kernel<2, true ><<<gN, GEMM_THREADS, GEMM_SMEM>>>(pagg, WT(0), atom_b1, ptmp, N);
    gemm_kernel<0, false><<<gN, GEMM_THREADS, GEMM_SMEM>>>(ptmp, WT(1), atom_b2, phA, N);

    // ---- bond encode: e = enc(edge_attr) ----
    embed_ln_kernel<<<E, 256>>>(edge_attr, bond_emb, bond_ln_g, bond_ln_b, pe, 3, 8);
    gemm_kernel<2, true ><<<gE, GEMM_THREADS, GEMM_SMEM>>>(pe,   WT(2), bond_b1, ptmp, E);
    gemm_kernel<0, false><<<gE, GEMM_THREADS, GEMM_SMEM>>>(ptmp, WT(3), bond_b2, pe, E);

    // ---- init agg = h for layer 0 ----
    int n4 = N * D / 4;
    copy_kernel<<<(n4 + 255) / 256, 256>>>((const float4*)phA, (float4*)pagg, n4);

    const float* hcur = phA;
    float* hnext = phB;
    for (int l = 0; l < N_LAYERS; l++) {
        // agg += relu(h[src] + e)   (agg pre-initialized to h -> z = h + sum msg)
        edge_msg_kernel<<<E, 192>>>(edge_index, hcur, pe, pagg, E);
        // tf32-round agg in place so the GEMM's tf32 truncation is lossless
        round_tf32_kernel<<<(n4 + 255) / 256, 256>>>((float4*)pagg, n4);
        // conv MLP
        gemm_kernel<1, true ><<<gN, GEMM_THREADS, GEMM_SMEM>>>(pagg, WT(4 + l), conv_b1 + l * D, ptmp, N);
        gemm_kernel<0, false><<<gN, GEMM_THREADS, GEMM_SMEM>>>(ptmp, WT(8 + l), conv_b2 + l * D, pagg, N);
        // h = LN(gelu(z) + h_in); also seed next layer's agg
        float* dst  = (l == N_LAYERS - 1) ? out : hnext;
        float* aggc = (l == N_LAYERS - 1) ? nullptr : pagg;
        ln_res_kernel<<<N, 256>>>(pagg, hcur, ln_g + l * D, ln_b + l * D, dst, aggc);

        float* old = (float*)hcur;
        hcur = dst;
        hnext = old;
    }
}

// round 9
// speedup vs baseline: 1.4463x; 1.4463x over previous
#include <cuda_runtime.h>
#include <cuda_fp16.h>
#include <cstdint>
#include <cstddef>

#define D 768
#define N_LAYERS 4
#define MAXN 50000
#define MAXE 100000

// ---------------- static scratch (allocation-free rule) ----------------
__device__ float  g_e  [(size_t)MAXE * D];   // bond/edge features e  [E,768] fp32
__device__ float  g_hA [(size_t)MAXN * D];
__device__ float  g_hB [(size_t)MAXN * D];
__device__ float  g_agg[(size_t)MAXN * D];
__device__ __align__(128) __half g_a16[(size_t)MAXE * D];  // GEMM-1 inputs (fp16)
__device__ __align__(128) __half g_t16[(size_t)MAXE * D];  // hidden activations (fp16)
__device__ __align__(128) __half g_w16[(size_t)12 * D * D]; // transposed fp16 weights [n][k]

// ---------------- tiny helpers ----------------
__device__ __forceinline__ float gelu_f(float x) {
    const float k0 = 0.7978845608028654f;
    const float k1 = 0.044715f;
    return 0.5f * x * (1.0f + tanhf(k0 * (x + k1 * x * x * x)));
}
template <int ACT>
__device__ __forceinline__ float actf(float x) {
    if (ACT == 1) return fmaxf(x, 0.0f);
    if (ACT == 2) return gelu_f(x);
    return x;
}
__device__ __forceinline__ void block_reduce2(float& s1, float& s2, float* shm) {
    #pragma unroll
    for (int o = 16; o > 0; o >>= 1) {
        s1 += __shfl_xor_sync(0xffffffffu, s1, o);
        s2 += __shfl_xor_sync(0xffffffffu, s2, o);
    }
    int wid = threadIdx.x >> 5, lane = threadIdx.x & 31;
    if (lane == 0) { shm[wid] = s1; shm[8 + wid] = s2; }
    __syncthreads();
    float a = 0.f, b = 0.f;
    #pragma unroll
    for (int i = 0; i < 8; i++) { a += shm[i]; b += shm[8 + i]; }
    s1 = a; s2 = b;
}

__device__ __forceinline__ void cp_async16(void* s, const void* g) {
    uint32_t sa = (uint32_t)__cvta_generic_to_shared(s);
    asm volatile("cp.async.cg.shared.global [%0], [%1], 16;" :: "r"(sa), "l"(g));
}
__device__ __forceinline__ void ldsm_x4(uint32_t* r, uint32_t addr) {
    asm volatile("ldmatrix.sync.aligned.m8n8.x4.shared.b16 {%0,%1,%2,%3}, [%4];"
                 : "=r"(r[0]), "=r"(r[1]), "=r"(r[2]), "=r"(r[3]) : "r"(addr));
}
__device__ __forceinline__ void mma_f16(float* c, const uint32_t* a, uint32_t b0, uint32_t b1) {
    asm volatile(
        "mma.sync.aligned.m16n8k16.row.col.f32.f16.f16.f32 "
        "{%0,%1,%2,%3},{%4,%5,%6,%7},{%8,%9},{%0,%1,%2,%3};"
        : "+f"(c[0]), "+f"(c[1]), "+f"(c[2]), "+f"(c[3])
        : "r"(a[0]), "r"(a[1]), "r"(a[2]), "r"(a[3]), "r"(b0), "r"(b1));
}

// ---------------- fp16 tensor-core GEMM ----------------
// C[M,768] = act(A[M,768] @ Wt^T + bias); A fp16 row-major, Wt fp16 [N][K] row-major.
// CTA tile 128(M) x 256(N), 512 threads (warps 4M x 4N, warp tile 32x64),
// BK=32 halves, 4-stage cp.async pipeline, ldmatrix operand loads.
#define BM 128
#define BN 256
#define BK 32
#define NT (D / BK)                      // 24
#define NSTAGE 4
#define SROW 80                          // smem row pitch bytes (40 halves) -> LDSM conflict-free
#define A_BYTES (BM * SROW)              // 10240
#define STAGE_BYTES (A_BYTES + BN * SROW)  // 30720
#define GEMM_THREADS 512
#define GEMM_SMEM (NSTAGE * STAGE_BYTES)   // 122880

template <int ACT, bool HOUT>
__global__ void __launch_bounds__(GEMM_THREADS, 1)
gemm_kernel(const __half* __restrict__ A, const __half* __restrict__ Wt,
            const float* __restrict__ bias, void* __restrict__ Cv, int M)
{
    extern __shared__ char smem[];
    const int t  = threadIdx.x;
    const int m0 = blockIdx.y * BM;
    const int n0 = blockIdx.x * BN;
    const uint32_t sbu = (uint32_t)__cvta_generic_to_shared(smem);

    auto load_stage = [&](int s, int kt) {
        char* abuf = smem + s * STAGE_BYTES;
        char* bbuf = abuf + A_BYTES;
        {   // A: 128 rows x 64B = 512 chunks, 1/thread
            int row = t >> 2, c = t & 3;
            int m = m0 + row; m = (m < M) ? m : (M - 1);
            cp_async16(abuf + row * SROW + c * 16, A + (size_t)m * D + kt * BK + c * 8);
        }
        #pragma unroll
        for (int i = 0; i < 2; i++) {   // B: 256 rows x 64B = 1024 chunks
            int q = t + i * GEMM_THREADS;
            int row = q >> 2, c = q & 3;
            cp_async16(bbuf + row * SROW + c * 16, Wt + (size_t)(n0 + row) * D + kt * BK + c * 8);
        }
    };

    float acc[2][8][4];
    #pragma unroll
    for (int i = 0; i < 2; i++)
        #pragma unroll
        for (int j = 0; j < 8; j++)
            #pragma unroll
            for (int k = 0; k < 4; k++) acc[i][j][k] = 0.f;

    #pragma unroll
    for (int s = 0; s < NSTAGE; s++) {
        load_stage(s, s);
        asm volatile("cp.async.commit_group;" ::: "memory");
    }

    const int lane = t & 31, wid = t >> 5;
    const int wm = (wid & 3) * 32;      // warp M offset (4 warps over 128)
    const int wn = (wid >> 2) * 64;     // warp N offset (4 warps over 256)
    const int gr = lane >> 2, tig = lane & 3;

    // per-thread ldmatrix row offsets (bytes within tile)
    const uint32_t a_off0 = (uint32_t)((wm + (lane & 15)) * SROW + (lane >> 4) * 16);
    const uint32_t b_off0 = (uint32_t)((wn + (lane & 7) + ((lane >> 4) & 1) * 8) * SROW
                                       + ((lane >> 3) & 1) * 16);

    for (int kt = 0; kt < NT; ++kt) {
        const int s = kt % NSTAGE;
        asm volatile("cp.async.wait_group %0;" :: "n"(NSTAGE - 1) : "memory");
        __syncthreads();
        const uint32_t sa = sbu + s * STAGE_BYTES;
        const uint32_t sb = sa + A_BYTES;
        #pragma unroll
        for (int kc = 0; kc < 2; kc++) {           // two k16 sub-tiles
            uint32_t af[2][4];
            #pragma unroll
            for (int mi = 0; mi < 2; mi++)
                ldsm_x4(af[mi], sa + a_off0 + mi * 16 * SROW + kc * 32);
            #pragma unroll
            for (int jp = 0; jp < 4; jp++) {       // pairs of n-tiles
                uint32_t bf[4];
                ldsm_x4(bf, sb + b_off0 + jp * 16 * SROW + kc * 32);
                mma_f16(acc[0][jp * 2 + 0], af[0], bf[0], bf[1]);
                mma_f16(acc[1][jp * 2 + 0], af[1], bf[0], bf[1]);
                mma_f16(acc[0][jp * 2 + 1], af[0], bf[2], bf[3]);
                mma_f16(acc[1][jp * 2 + 1], af[1], bf[2], bf[3]);
            }
        }
        __syncthreads();                 // stage fully consumed before refill
        if (kt + NSTAGE < NT) load_stage(s, kt + NSTAGE);
        asm volatile("cp.async.commit_group;" ::: "memory");
    }

    // epilogue: bias + activation + store (fp16 for hidden, fp32 for final)
    #pragma unroll
    for (int mi = 0; mi < 2; mi++) {
        int row0 = m0 + wm + mi * 16 + gr;
        #pragma unroll
        for (int ni = 0; ni < 8; ni++) {
            int col = n0 + wn + ni * 8 + tig * 2;
            float bv0 = __ldg(bias + col), bv1 = __ldg(bias + col + 1);
            float v0 = actf<ACT>(acc[mi][ni][0] + bv0);
            float v1 = actf<ACT>(acc[mi][ni][1] + bv1);
            float v2 = actf<ACT>(acc[mi][ni][2] + bv0);
            float v3 = actf<ACT>(acc[mi][ni][3] + bv1);
            if (HOUT) {
                __half* C = (__half*)Cv;
                if (row0 < M)
                    *(__half2*)(C + (size_t)row0 * D + col) = __floats2half2_rn(v0, v1);
                if (row0 + 8 < M)
                    *(__half2*)(C + (size_t)(row0 + 8) * D + col) = __floats2half2_rn(v2, v3);
            } else {
                float* C = (float*)Cv;
                if (row0 < M)
                    *(float2*)(C + (size_t)row0 * D + col) = make_float2(v0, v1);
                if (row0 + 8 < M)
                    *(float2*)(C + (size_t)(row0 + 8) * D + col) = make_float2(v2, v3);
            }
        }
    }
}

// ---------------- weight transpose + fp16 convert, all 12 matrices in ONE launch ----------------
struct WPtrs { const float* p[6]; };   // atom_w1, atom_w2, bond_w1, bond_w2, conv_w1, conv_w2
__global__ void transpose_all_kernel(WPtrs w, __half* __restrict__ wt) {
    int mat = blockIdx.z;
    const float* W = (mat < 4) ? w.p[mat]
                   : (mat < 8) ? w.p[4] + (size_t)(mat - 4) * D * D
                               : w.p[5] + (size_t)(mat - 8) * D * D;
    __half* Wt = wt + (size_t)mat * D * D;
    __shared__ float tile[32][33];
    int bx = blockIdx.x * 32;   // n block
    int by = blockIdx.y * 32;   // k block
    int tx = threadIdx.x, ty = threadIdx.y;   // 32 x 8
    #pragma unroll
    for (int j = 0; j < 32; j += 8)
        tile[ty + j][tx] = W[(size_t)(by + ty + j) * D + bx + tx];   // tile[k][n]
    __syncthreads();
    #pragma unroll
    for (int j = 0; j < 32; j += 8)
        Wt[(size_t)(bx + ty + j) * D + by + tx] = __float2half_rn(tile[tx][ty + j]);
}

// ---------------- fp32 -> fp16 convert (agg before conv GEMM) ----------------
__global__ void cvt_half_kernel(const float4* __restrict__ src, __half2* __restrict__ dst, int n4) {
    int i = blockIdx.x * blockDim.x + threadIdx.x;
    if (i < n4) {
        float4 v = src[i];
        dst[i * 2 + 0] = __floats2half2_rn(v.x, v.y);
        dst[i * 2 + 1] = __floats2half2_rn(v.z, v.w);
    }
}

// ---------------- embedding sum + LayerNorm (fp16 output for GEMM) ----------------
__global__ void embed_ln_kernel(const int* __restrict__ ids,
                                const float* __restrict__ emb,
                                const float* __restrict__ g,
                                const float* __restrict__ bta,
                                __half* __restrict__ out,
                                int F, int V) {
    int n = blockIdx.x;
    int t = threadIdx.x;
    __shared__ int   sid[16];
    __shared__ float shm[16];
    if (t < F) sid[t] = ids[(size_t)n * F + t];
    __syncthreads();

    float x[3];
    #pragma unroll
    for (int j = 0; j < 3; j++) {
        int d = t + j * 256;
        float s = 0.f;
        for (int f = 0; f < F; f++)
            s += emb[((size_t)(f * V + sid[f])) * D + d];
        x[j] = s;
    }
    float s1 = x[0] + x[1] + x[2];
    float s2 = x[0]*x[0] + x[1]*x[1] + x[2]*x[2];
    block_reduce2(s1, s2, shm);
    float mean = s1 * (1.0f / D);
    float var  = s2 * (1.0f / D) - mean * mean;
    float inv  = rsqrtf(var + 1e-5f);
    __half* o = out + (size_t)n * D;
    #pragma unroll
    for (int j = 0; j < 3; j++) {
        int d = t + j * 256;
        o[d] = __float2half_rn((x[j] - mean) * inv * g[d] + bta[d]);
    }
}

// ---------------- edge message: agg[dst] += relu(h[src] + e) ----------------
__global__ void edge_msg_kernel(const int* __restrict__ ei,
                                const float* __restrict__ h,
                                const float* __restrict__ e,
                                float* __restrict__ agg, int E) {
    int eid = blockIdx.x;
    int src = __ldg(ei + eid);
    int dst = __ldg(ei + E + eid);
    int t = threadIdx.x;  // 192 threads * float4 = 768
    float4 hv = *((const float4*)(h + (size_t)src * D) + t);
    float4 ev = *((const float4*)(e + (size_t)eid * D) + t);
    float4 m;
    m.x = fmaxf(hv.x + ev.x, 0.f);
    m.y = fmaxf(hv.y + ev.y, 0.f);
    m.z = fmaxf(hv.z + ev.z, 0.f);
    m.w = fmaxf(hv.w + ev.w, 0.f);
    float* a = agg + (size_t)dst * D + t * 4;
    atomicAdd(a + 0, m.x);
    atomicAdd(a + 1, m.y);
    atomicAdd(a + 2, m.z);
    atomicAdd(a + 3, m.w);
}

// ---------------- fused gelu + residual + LayerNorm (+ agg init for next layer) ----------------
__global__ void ln_res_kernel(const float* __restrict__ z,
                              const float* __restrict__ hin,
                              const float* __restrict__ g,
                              const float* __restrict__ bta,
                              float* __restrict__ out,
                              float* __restrict__ aggc) {
    int n = blockIdx.x;
    int t = threadIdx.x;
    __shared__ float shm[16];
    float x[3];
    #pragma unroll
    for (int j = 0; j < 3; j++) {
        int d = t + j * 256;
        x[j] = gelu_f(z[(size_t)n * D + d]) + hin[(size_t)n * D + d];
    }
    float s1 = x[0] + x[1] + x[2];
    float s2 = x[0]*x[0] + x[1]*x[1] + x[2]*x[2];
    block_reduce2(s1, s2, shm);
    float mean = s1 * (1.0f / D);
    float var  = s2 * (1.0f / D) - mean * mean;
    float inv  = rsqrtf(var + 1e-5f);
    #pragma unroll
    for (int j = 0; j < 3; j++) {
        int d = t + j * 256;
        float r = (x[j] - mean) * inv * g[d] + bta[d];
        out[(size_t)n * D + d] = r;
        if (aggc) aggc[(size_t)n * D + d] = r;
    }
}

__global__ void copy_kernel(const float4* __restrict__ src, float4* __restrict__ dst, int n4) {
    int i = blockIdx.x * blockDim.x + threadIdx.x;
    if (i < n4) dst[i] = src[i];
}

// ---------------- host orchestration ----------------
extern "C" void kernel_launch(void* const* d_in, const int* in_sizes, int n_in,
                              void* d_out, int out_size) {
    const int*   x          = (const int*)d_in[0];
    const int*   edge_attr  = (const int*)d_in[1];
    const int*   edge_index = (const int*)d_in[2];
    const float* atom_emb   = (const float*)d_in[3];
    const float* atom_ln_g  = (const float*)d_in[4];
    const float* atom_ln_b  = (const float*)d_in[5];
    const float* atom_w1    = (const float*)d_in[6];
    const float* atom_b1    = (const float*)d_in[7];
    const float* atom_w2    = (const float*)d_in[8];
    const float* atom_b2    = (const float*)d_in[9];
    const float* bond_emb   = (const float*)d_in[10];
    const float* bond_ln_g  = (const float*)d_in[11];
    const float* bond_ln_b  = (const float*)d_in[12];
    const float* bond_w1    = (const float*)d_in[13];
    const float* bond_b1    = (const float*)d_in[14];
    const float* bond_w2    = (const float*)d_in[15];
    const float* bond_b2    = (const float*)d_in[16];
    const float* conv_w1    = (const float*)d_in[17];
    const float* conv_b1    = (const float*)d_in[18];
    const float* conv_w2    = (const float*)d_in[19];
    const float* conv_b2    = (const float*)d_in[20];
    const float* ln_g       = (const float*)d_in[21];
    const float* ln_b       = (const float*)d_in[22];
    float* out = (float*)d_out;

    int N = in_sizes[0] / 9;
    int E = in_sizes[1] / 3;
    if (N > MAXN) N = MAXN;
    if (E > MAXE) E = MAXE;

    float *pe, *phA, *phB, *pagg;
    __half *pa16, *pt16, *pw16;
    cudaGetSymbolAddress((void**)&pe,   g_e);
    cudaGetSymbolAddress((void**)&phA,  g_hA);
    cudaGetSymbolAddress((void**)&phB,  g_hB);
    cudaGetSymbolAddress((void**)&pagg, g_agg);
    cudaGetSymbolAddress((void**)&pa16, g_a16);
    cudaGetSymbolAddress((void**)&pt16, g_t16);
    cudaGetSymbolAddress((void**)&pw16, g_w16);

    cudaFuncSetAttribute(gemm_kernel<0, false>, cudaFuncAttributeMaxDynamicSharedMemorySize, GEMM_SMEM);
    cudaFuncSetAttribute(gemm_kernel<1, true>,  cudaFuncAttributeMaxDynamicSharedMemorySize, GEMM_SMEM);
    cudaFuncSetAttribute(gemm_kernel<2, true>,  cudaFuncAttributeMaxDynamicSharedMemorySize, GEMM_SMEM);

    // ---- launch 0: transpose + fp16-convert all 12 weight matrices ----
    WPtrs wp;
    wp.p[0] = atom_w1; wp.p[1] = atom_w2; wp.p[2] = bond_w1;
    wp.p[3] = bond_w2; wp.p[4] = conv_w1; wp.p[5] = conv_w2;
    transpose_all_kernel<<<dim3(D / 32, D / 32, 12), dim3(32, 8)>>>(wp, pw16);

    auto WT = [&](int i) { return pw16 + (size_t)i * D * D; };
    dim3 gN(D / BN, (N + BM - 1) / BM);
    dim3 gE(D / BN, (E + BM - 1) / BM);

    // ---- atom encode: h = enc(x) ----
    embed_ln_kernel<<<N, 256>>>(x, atom_emb, atom_ln_g, atom_ln_b, pa16, 9, 128);
    gemm_kernel<2, true ><<<gN, GEMM_THREADS, GEMM_SMEM>>>(pa16, WT(0), atom_b1, pt16, N);
    gemm_kernel<0, false><<<gN, GEMM_THREADS, GEMM_SMEM>>>(pt16, WT(1), atom_b2, phA, N);

    // ---- bond encode: e = enc(edge_attr) ----
    embed_ln_kernel<<<E, 256>>>(edge_attr, bond_emb, bond_ln_g, bond_ln_b, pa16, 3, 8);
    gemm_kernel<2, true ><<<gE, GEMM_THREADS, GEMM_SMEM>>>(pa16, WT(2), bond_b1, pt16, E);  // launch #5 -> ncu
    gemm_kernel<0, false><<<gE, GEMM_THREADS, GEMM_SMEM>>>(pt16, WT(3), bond_b2, pe, E);

    // ---- init agg = h for layer 0 ----
    int n4 = N * D / 4;
    copy_kernel<<<(n4 + 255) / 256, 256>>>((const float4*)phA, (float4*)pagg, n4);

    const float* hcur = phA;
    float* hnext = phB;
    for (int l = 0; l < N_LAYERS; l++) {
        // agg += relu(h[src] + e)   (agg pre-initialized to h -> z = h + sum msg)
        edge_msg_kernel<<<E, 192>>>(edge_index, hcur, pe, pagg, E);
        // convert z (=agg) to fp16 for the conv GEMM
        cvt_half_kernel<<<(n4 + 255) / 256, 256>>>((const float4*)pagg, (__half2*)pa16, n4);
        // conv MLP
        gemm_kernel<1, true ><<<gN, GEMM_THREADS, GEMM_SMEM>>>(pa16, WT(4 + l), conv_b1 + l * D, pt16, N);
        gemm_kernel<0, false><<<gN, GEMM_THREADS, GEMM_SMEM>>>(pt16, WT(8 + l), conv_b2 + l * D, pagg, N);
        // h = LN(gelu(z) + h_in); also seed next layer's agg
        float* dst  = (l == N_LAYERS - 1) ? out : hnext;
        float* aggc = (l == N_LAYERS - 1) ? nullptr : pagg;
        ln_res_kernel<<<N, 256>>>(pagg, hcur, ln_g + l * D, ln_b + l * D, dst, aggc);

        float* old = (float*)hcur;
        hcur = dst;
        hnext = old;
    }
}